// round 1
// baseline (speedup 1.0000x reference)
#include <cuda_runtime.h>
#include <cstdint>

// Problem constants
#define HS_B 16
#define HS_C 256      // = D
#define HS_HW 1024    // 32*32
#define N_ROWS 16384  // B*H*W
#define KC 8192       // codebook size
#define D 256

// Output layout (concatenated float32): quant_out [B,C,H,W] | loss | min_idx [B, H*W]
#define LOSS_OFF  4194304
#define IDX_OFF   4194305

// GEMM tiling
#define BM 128
#define BN 128
#define BD 32
#define NT 256
#define NUM_CHUNKS ((KC / BN) * (D / BD))   // 64 * 8 = 512

// Scratch (no cudaMalloc allowed)
__device__ float g_ET[(size_t)D * KC];   // E transposed: [d][k]
__device__ float g_enorm[KC];

// smem layout (floats): sX[256][128]=32768 | sE 2x[32][128]=8192 | sBest 128 ull (256f) | sIdx 128 int (128f) | sRed 8f
#define SMEM_FLOATS (32768 + 8192 + 256 + 128 + 8)
#define SMEM_BYTES (SMEM_FLOATS * 4)

__global__ void zero_loss_kernel(float* out) { out[LOSS_OFF] = 0.0f; }

__global__ void transposeE_kernel(const float* __restrict__ E) {
    __shared__ float tile[32][33];
    int kb = blockIdx.x * 32, db = blockIdx.y * 32;
    int tx = threadIdx.x, ty = threadIdx.y;   // 32 x 8
    #pragma unroll
    for (int i = 0; i < 32; i += 8)
        tile[ty + i][tx] = E[(size_t)(kb + ty + i) * D + db + tx];
    __syncthreads();
    #pragma unroll
    for (int i = 0; i < 32; i += 8)
        g_ET[(size_t)(db + ty + i) * KC + kb + tx] = tile[tx][ty + i];
}

__global__ void enorm_kernel(const float* __restrict__ E) {
    int k = blockIdx.x * 8 + (threadIdx.x >> 5);
    int lane = threadIdx.x & 31;
    const float4* p = (const float4*)(E + (size_t)k * D);
    float4 v0 = p[lane * 2], v1 = p[lane * 2 + 1];
    float s = v0.x*v0.x + v0.y*v0.y + v0.z*v0.z + v0.w*v0.w
            + v1.x*v1.x + v1.y*v1.y + v1.z*v1.z + v1.w*v1.w;
    #pragma unroll
    for (int o = 16; o > 0; o >>= 1) s += __shfl_xor_sync(0xffffffffu, s, o);
    if (lane == 0) g_enorm[k] = s;
}

__device__ __forceinline__ void cpasync16(float* sdst, const float* gsrc) {
    uint32_t sa = (uint32_t)__cvta_generic_to_shared(sdst);
    asm volatile("cp.async.cg.shared.global [%0], [%1], 16;" :: "r"(sa), "l"(gsrc));
}

// Load E chunk g (ct = g>>3 code tile, dc = g&7 depth chunk) into sEb [32][128]
__device__ __forceinline__ void load_echunk(float* sEb, int g) {
    int ct = g >> 3, dc = g & 7;
    const float* src0 = g_ET + (size_t)(dc * BD) * KC + ct * BN;
    #pragma unroll
    for (int k = 0; k < 4; k++) {
        int j = threadIdx.x + k * NT;
        int dd = j >> 5, kk = (j & 31) * 4;
        cpasync16(sEb + dd * BN + kk, src0 + (size_t)dd * KC + kk);
    }
    asm volatile("cp.async.commit_group;");
}

__global__ void __launch_bounds__(NT, 1)
vq_main_kernel(const float* __restrict__ hs, const float* __restrict__ E,
               float* __restrict__ out) {
    extern __shared__ float smem[];
    float* sX = smem;                                   // [d][r] 256x128
    float* sE = smem + 32768;                           // double buffer 2 x [32][128]
    unsigned long long* sBest = (unsigned long long*)(smem + 32768 + 8192);
    int* sIdx = (int*)(smem + 32768 + 8192 + 256);
    float* sRed = smem + 32768 + 8192 + 256 + 128;

    const int tid = threadIdx.x;
    const int row0 = blockIdx.x * BM;
    const int b = row0 >> 10;
    const int p0 = row0 & 1023;
    const size_t xbase = (size_t)b * HS_C * HS_HW + p0;  // + d*1024 + r

    if (tid < BM) sBest[tid] = 0xFFFFFFFFFFFFFFFFull;

    // Load x tile: hs is [B][C][H*W] -> already [d][n] for fixed b. Fully coalesced.
    #pragma unroll
    for (int k = 0; k < 32; k++) {
        int j = tid + k * NT;           // float4 index
        int d = j >> 5;
        int rq = (j & 31) * 4;
        float4 v = *(const float4*)(hs + xbase + (size_t)d * HS_HW + rq);
        *(float4*)(sX + d * BM + rq) = v;
    }

    load_echunk(sE, 0);

    const int tx = tid & 15, ty = tid >> 4;
    const int r0 = ty * 8;
    const float4* sX4 = (const float4*)sX;

    for (int ct = 0; ct < KC / BN; ct++) {
        float acc[8][8];
        #pragma unroll
        for (int i = 0; i < 8; i++)
            #pragma unroll
            for (int j = 0; j < 8; j++) acc[i][j] = 0.0f;

        for (int dc = 0; dc < 8; dc++) {
            int g = ct * 8 + dc;
            asm volatile("cp.async.wait_group 0;" ::: "memory");
            __syncthreads();
            if (g + 1 < NUM_CHUNKS) load_echunk(sE + ((g + 1) & 1) * 4096, g + 1);
            const float* sEb = sE + (g & 1) * 4096;

            #pragma unroll 4
            for (int dd = 0; dd < BD; dd++) {
                float4 a0 = sX4[(dc * BD + dd) * 32 + ty * 2];
                float4 a1 = sX4[(dc * BD + dd) * 32 + ty * 2 + 1];
                float4 b0 = *(const float4*)(sEb + dd * BN + tx * 8);
                float4 b1 = *(const float4*)(sEb + dd * BN + tx * 8 + 4);
                float av[8] = {a0.x, a0.y, a0.z, a0.w, a1.x, a1.y, a1.z, a1.w};
                float bv[8] = {b0.x, b0.y, b0.z, b0.w, b1.x, b1.y, b1.z, b1.w};
                #pragma unroll
                for (int i = 0; i < 8; i++)
                    #pragma unroll
                    for (int j = 0; j < 8; j++)
                        acc[i][j] += av[i] * bv[j];
            }
        }

        // Tile epilogue: dist = ||e||^2 - 2 x.e ; running argmin per row
        int c0 = ct * BN + tx * 8;
        float4 e0 = *(const float4*)(g_enorm + c0);
        float4 e1 = *(const float4*)(g_enorm + c0 + 4);
        float en[8] = {e0.x, e0.y, e0.z, e0.w, e1.x, e1.y, e1.z, e1.w};
        #pragma unroll
        for (int i = 0; i < 8; i++) {
            unsigned long long best = 0xFFFFFFFFFFFFFFFFull;
            #pragma unroll
            for (int j = 0; j < 8; j++) {
                float dist = fmaf(-2.0f, acc[i][j], en[j]);
                unsigned u = __float_as_uint(dist);
                u = (u & 0x80000000u) ? ~u : (u | 0x80000000u);
                unsigned long long pk = ((unsigned long long)u << 32) | (unsigned)(c0 + j);
                best = min(best, pk);
            }
            atomicMin(&sBest[r0 + i], best);
        }
    }

    __syncthreads();
    if (tid < BM) {
        unsigned long long bb = sBest[tid];
        int k = (int)(bb & 0xFFFFFFFFu);
        sIdx[tid] = k;
        out[IDX_OFF + row0 + tid] = (float)k;
    }
    __syncthreads();

    // quant gather + loss. Writes coalesced (r fast, matches [B,C,HW] layout).
    float lsum = 0.0f;
    for (int i = 0; i < 128; i++) {
        int lin = i * NT + tid;
        int c = lin >> 7;
        int r = lin & 127;
        int k = sIdx[r];
        float ev = __ldg(E + (size_t)k * D + c);
        size_t ad = xbase + (size_t)c * HS_HW + r;
        float xv = hs[ad];
        out[ad] = ev;
        float dlt = ev - xv;
        lsum = fmaf(dlt, dlt, lsum);
    }
    #pragma unroll
    for (int o = 16; o > 0; o >>= 1) lsum += __shfl_xor_sync(0xffffffffu, lsum, o);
    int wid = tid >> 5;
    if ((tid & 31) == 0) sRed[wid] = lsum;
    __syncthreads();
    if (tid == 0) {
        float tot = 0.0f;
        #pragma unroll
        for (int w = 0; w < 8; w++) tot += sRed[w];
        // loss = (1 + 0.25) * mean(sq) over 4194304 elements
        atomicAdd(out + LOSS_OFF, tot * (1.25f / 4194304.0f));
    }
}

extern "C" void kernel_launch(void* const* d_in, const int* in_sizes, int n_in,
                              void* d_out, int out_size) {
    const float* hs = (const float*)d_in[0];   // [16,256,32,32]
    const float* E  = (const float*)d_in[1];   // [8192,256]
    float* out = (float*)d_out;

    cudaFuncSetAttribute(vq_main_kernel,
                         cudaFuncAttributeMaxDynamicSharedMemorySize, SMEM_BYTES);

    zero_loss_kernel<<<1, 1>>>(out);
    transposeE_kernel<<<dim3(KC / 32, D / 32), dim3(32, 8)>>>(E);
    enorm_kernel<<<KC / 8, 256>>>(E);
    vq_main_kernel<<<N_ROWS / BM, NT, SMEM_BYTES>>>(hs, E, out);
}

// round 3
// speedup vs baseline: 3.7390x; 3.7390x over previous
#include <cuda_runtime.h>
#include <cuda_fp16.h>
#include <cstdint>

// ---------------- problem constants ----------------
#define N_ROWS 16384
#define KC 8192
#define D 256
#define LOSS_OFF 4194304
#define IDX_OFF 4194305

typedef unsigned long long u64;

// ---------------- device scratch ----------------
__device__ __half g_Ah[(size_t)N_ROWS * D];   // x fp16 [m][k]
__device__ __half g_Bh[(size_t)KC * D];       // e fp16 [n][k]
__device__ float g_en2[KC];                   // ||e||^2 fp32
__device__ float g_xn2[N_ROWS];               // ||x||^2 fp32
__device__ float g_thrpad;                    // 2*E_max threshold pad
__device__ u64 g_part[(size_t)N_ROWS * 128];  // per row: 64 tiles x top-2
__device__ int g_idx[N_ROWS];

// ---------------- helpers ----------------
__device__ __forceinline__ uint32_t smem_u32(const void* p) {
    uint32_t a;
    asm("{ .reg .u64 t; cvta.to.shared.u64 t, %1; cvt.u32.u64 %0, t; }" : "=r"(a) : "l"(p));
    return a;
}
__device__ __forceinline__ u64 packdi(float d, int idx) {
    uint32_t u = __float_as_uint(d);
    u = (u & 0x80000000u) ? ~u : (u | 0x80000000u);
    return ((u64)u << 32) | (uint32_t)idx;
}
__device__ __forceinline__ float unpackd(u64 p) {
    uint32_t u = (uint32_t)(p >> 32);
    u = (u & 0x80000000u) ? (u ^ 0x80000000u) : ~u;
    return __uint_as_float(u);
}
__device__ __forceinline__ void cpasync16(uint32_t sdst, const void* gsrc) {
    asm volatile("cp.async.cg.shared.global [%0], [%1], 16;" :: "r"(sdst), "l"(gsrc));
}
__device__ __forceinline__ void ldmx4(uint32_t addr, uint32_t& r0, uint32_t& r1,
                                      uint32_t& r2, uint32_t& r3) {
    asm volatile("ldmatrix.sync.aligned.m8n8.x4.shared.b16 {%0,%1,%2,%3}, [%4];"
                 : "=r"(r0), "=r"(r1), "=r"(r2), "=r"(r3) : "r"(addr));
}
__device__ __forceinline__ void mma16816(float* c, const uint32_t* a, const uint32_t* b) {
    asm volatile(
        "mma.sync.aligned.m16n8k16.row.col.f32.f16.f16.f32 "
        "{%0,%1,%2,%3}, {%4,%5,%6,%7}, {%8,%9}, {%0,%1,%2,%3};"
        : "+f"(c[0]), "+f"(c[1]), "+f"(c[2]), "+f"(c[3])
        : "r"(a[0]), "r"(a[1]), "r"(a[2]), "r"(a[3]), "r"(b[0]), "r"(b[1]));
}

// ---------------- prep kernels ----------------
__global__ void init_kernel(float* out) {
    int i = blockIdx.x * 256 + threadIdx.x;
    if (i < N_ROWS) g_xn2[i] = 0.0f;
    if (i == 0) out[LOSS_OFF] = 0.0f;
}

__global__ void enorm_kernel(const float* __restrict__ E) {
    int k = blockIdx.x * 8 + (threadIdx.x >> 5);
    int lane = threadIdx.x & 31;
    const float4* p = (const float4*)(E + (size_t)k * D);
    float4 v0 = p[lane * 2], v1 = p[lane * 2 + 1];
    float s = v0.x*v0.x + v0.y*v0.y + v0.z*v0.z + v0.w*v0.w
            + v1.x*v1.x + v1.y*v1.y + v1.z*v1.z + v1.w*v1.w;
    #pragma unroll
    for (int o = 16; o > 0; o >>= 1) s += __shfl_xor_sync(0xffffffffu, s, o);
    if (lane == 0) g_en2[k] = s;
}

__global__ void prepB_kernel(const float* __restrict__ E) {
    int i = blockIdx.x * 256 + threadIdx.x;   // float4 index, 524288 total
    float4 v = *((const float4*)E + i);
    __half2 h0 = __floats2half2_rn(v.x, v.y);
    __half2 h1 = __floats2half2_rn(v.z, v.w);
    uint2 o; o.x = *(uint32_t*)&h0; o.y = *(uint32_t*)&h1;
    *((uint2*)g_Bh + i) = o;
}

// hs [b][c][hw] -> g_Ah [m][c] fp16 (m = b*1024 + hw), + row norms
__global__ void prepA_kernel(const float* __restrict__ hs) {
    __shared__ float tile[32][33];
    int m0 = blockIdx.x * 32, b = m0 >> 10, p0 = m0 & 1023;
    int c0 = blockIdx.y * 32;
    int tx = threadIdx.x, ty = threadIdx.y;   // 32 x 8
    float nacc = 0.0f;
    #pragma unroll
    for (int i = 0; i < 4; i++) {
        int c = c0 + ty + i * 8;
        float v = hs[((size_t)(b * 256 + c)) * 1024 + p0 + tx];
        tile[ty + i * 8][tx] = v;
        nacc = fmaf(v, v, nacc);               // contributes to row m0+tx
    }
    atomicAdd(&g_xn2[m0 + tx], nacc);
    __syncthreads();
    #pragma unroll
    for (int i = 0; i < 4; i++) {
        int row = ty + i * 8;
        g_Ah[(size_t)(m0 + row) * D + c0 + tx] = __float2half_rn(tile[tx][row]);
    }
}

__global__ void bound_kernel() {
    __shared__ float sred[8];
    int tid = threadIdx.x;
    float mx = 0.0f, me = 0.0f;
    for (int i = tid; i < N_ROWS; i += 256) mx = fmaxf(mx, g_xn2[i]);
    for (int i = tid; i < KC; i += 256) me = fmaxf(me, g_en2[i]);
    #pragma unroll
    for (int o = 16; o > 0; o >>= 1) {
        mx = fmaxf(mx, __shfl_xor_sync(0xffffffffu, mx, o));
        me = fmaxf(me, __shfl_xor_sync(0xffffffffu, me, o));
    }
    if ((tid & 31) == 0) sred[tid >> 5] = mx;
    __syncthreads();
    if (tid < 32) {
        mx = (tid < 8) ? sred[tid] : 0.0f;
        #pragma unroll
        for (int o = 4; o > 0; o >>= 1) mx = fmaxf(mx, __shfl_xor_sync(0xffffffffu, mx, o));
    }
    __syncthreads();
    if ((tid & 31) == 0) sred[tid >> 5] = me;
    __syncthreads();
    if (tid == 0) {
        me = fmaxf(fmaxf(fmaxf(sred[0], sred[1]), fmaxf(sred[2], sred[3])),
                   fmaxf(fmaxf(sred[4], sred[5]), fmaxf(sred[6], sred[7])));
        // 2*E_max: E_max ~ 2*(2^-10 + slack)*|x||e|; generous constant + abs slack
        g_thrpad = 0.006f * sqrtf(mx) * sqrtf(me) + 0.05f;
    }
}

// ---------------- main GEMM (fp16 mma.sync) ----------------
#define SA_OFF(b) ((b) * 16384)
#define SB_OFF(b) (32768 + (b) * 16384)
#define SEN_OFF   65536
#define SPART_OFF 66048
#define SMEM_SZ   (1024 + 66048 + 4096)

__global__ void __launch_bounds__(256, 2)
gemm_kernel() {
    extern __shared__ char smem_raw[];
    char* base = (char*)(((uintptr_t)smem_raw + 1023) & ~(uintptr_t)1023);
    uint32_t sb = smem_u32(base);
    float* sEn = (float*)(base + SEN_OFF);
    u64* sPart = (u64*)(base + SPART_OFF);

    const int tid = threadIdx.x;
    const int lane = tid & 31, wid = tid >> 5;
    const int wm = wid & 3, wn = wid >> 2;
    const int ntile = blockIdx.x, mtile = blockIdx.y;
    const int m0 = mtile * 128, n0 = ntile * 128;

    if (tid < 128) sEn[tid] = g_en2[n0 + tid];

    // chunk loader: 64 k's of A and B (16KB each) with XOR-8 swizzle
    const int ldrow = tid >> 3, ldkg = tid & 7;      // using idx=tid+it*256 below
    auto load_chunk = [&](int c, int bf) {
        #pragma unroll
        for (int it = 0; it < 4; it++) {
            int idx = tid + it * 256;
            int row = idx >> 3, kg = idx & 7;
            uint32_t soff = row * 128 + (((uint32_t)(kg ^ (row & 7))) << 4);
            cpasync16(sb + SA_OFF(bf) + soff,
                      g_Ah + (size_t)(m0 + row) * D + c * 64 + kg * 8);
            cpasync16(sb + SB_OFF(bf) + soff,
                      g_Bh + (size_t)(n0 + row) * D + c * 64 + kg * 8);
        }
        asm volatile("cp.async.commit_group;");
    };
    (void)ldrow; (void)ldkg;

    float acc[2][8][4];
    #pragma unroll
    for (int mt = 0; mt < 2; mt++)
        #pragma unroll
        for (int nt = 0; nt < 8; nt++)
            #pragma unroll
            for (int q = 0; q < 4; q++) acc[mt][nt][q] = 0.0f;

    load_chunk(0, 0);

    for (int c = 0; c < 4; c++) {
        if (c + 1 < 4) {
            load_chunk(c + 1, (c + 1) & 1);
            asm volatile("cp.async.wait_group 1;" ::: "memory");
        } else {
            asm volatile("cp.async.wait_group 0;" ::: "memory");
        }
        __syncthreads();
        uint32_t ab = sb + SA_OFF(c & 1), bbse = sb + SB_OFF(c & 1);
        #pragma unroll
        for (int ks = 0; ks < 4; ks++) {
            uint32_t a[2][4], bb[8][2];
            uint32_t kg = ks * 2 + (lane >> 4);
            uint32_t kx = ((kg ^ (lane & 7)) << 4);
            #pragma unroll
            for (int mt = 0; mt < 2; mt++) {
                uint32_t row = wm * 32 + mt * 16 + (lane & 15);
                ldmx4(ab + row * 128 + kx, a[mt][0], a[mt][1], a[mt][2], a[mt][3]);
            }
            #pragma unroll
            for (int nt2 = 0; nt2 < 4; nt2++) {
                uint32_t row = wn * 64 + nt2 * 16 + (lane & 15);
                uint32_t r0, r1, r2, r3;
                ldmx4(bbse + row * 128 + kx, r0, r1, r2, r3);
                bb[nt2 * 2][0] = r0; bb[nt2 * 2][1] = r2;
                bb[nt2 * 2 + 1][0] = r1; bb[nt2 * 2 + 1][1] = r3;
            }
            #pragma unroll
            for (int mt = 0; mt < 2; mt++)
                #pragma unroll
                for (int nt = 0; nt < 8; nt++)
                    mma16816(acc[mt][nt], a[mt], bb[nt]);
        }
        __syncthreads();
    }

    // epilogue: per-row top-2 of dist = en2 - 2*dot within this 128-col tile
    #pragma unroll
    for (int mt = 0; mt < 2; mt++) {
        #pragma unroll
        for (int half = 0; half < 2; half++) {
            u64 t1 = ~0ull, t2 = ~0ull;
            #pragma unroll
            for (int nt = 0; nt < 8; nt++) {
                #pragma unroll
                for (int cc = 0; cc < 2; cc++) {
                    int col = wn * 64 + nt * 8 + (lane & 3) * 2 + cc;
                    float dist = fmaf(-2.0f, acc[mt][nt][half * 2 + cc], sEn[col]);
                    u64 pk = packdi(dist, n0 + col);
                    if (pk < t1) { t2 = t1; t1 = pk; }
                    else if (pk < t2) { t2 = pk; }
                }
            }
            #pragma unroll
            for (int dlt = 1; dlt <= 2; dlt <<= 1) {
                u64 o1 = __shfl_xor_sync(0xffffffffu, t1, dlt);
                u64 o2 = __shfl_xor_sync(0xffffffffu, t2, dlt);
                u64 n1 = min(t1, o1);
                u64 n2 = min(max(t1, o1), min(t2, o2));
                t1 = n1; t2 = n2;
            }
            if ((lane & 3) == 0) {
                int rl = wm * 32 + mt * 16 + half * 8 + (lane >> 2);
                sPart[rl * 4 + wn * 2] = t1;
                sPart[rl * 4 + wn * 2 + 1] = t2;
            }
        }
    }
    __syncthreads();
    if (tid < 128) {
        u64 a1 = sPart[tid * 4], a2 = sPart[tid * 4 + 1];
        u64 b1 = sPart[tid * 4 + 2], b2 = sPart[tid * 4 + 3];
        u64 n1 = min(a1, b1);
        u64 n2 = min(max(a1, b1), min(a2, b2));
        g_part[(size_t)(m0 + tid) * 128 + ntile * 2] = n1;
        g_part[(size_t)(m0 + tid) * 128 + ntile * 2 + 1] = n2;
    }
}

// ---------------- merge + exact recheck ----------------
__device__ __forceinline__ u64 exact_pk(const float* __restrict__ E,
                                        const float xv[8], int lane, int k) {
    const float* ek = E + (size_t)k * D;
    float s = 0.0f;
    #pragma unroll
    for (int j = 0; j < 8; j++) s = fmaf(xv[j], __ldg(ek + lane + j * 32), s);
    #pragma unroll
    for (int o = 16; o > 0; o >>= 1) s += __shfl_xor_sync(0xffffffffu, s, o);
    float dist = fmaf(-2.0f, s, __ldg(&g_en2[k]));
    return packdi(dist, k);
}

__global__ void merge_kernel(const float* __restrict__ hs,
                             const float* __restrict__ E,
                             float* __restrict__ out) {
    int wid = threadIdx.x >> 5, lane = threadIdx.x & 31;
    int row = blockIdx.x * 8 + wid;
    int b = row >> 10, p = row & 1023;
    const float* xb = hs + (size_t)b * 256 * 1024 + p;
    float xv[8];
    #pragma unroll
    for (int j = 0; j < 8; j++) xv[j] = __ldg(xb + (size_t)(lane + j * 32) * 1024);

    u64 e[4];
    #pragma unroll
    for (int j = 0; j < 4; j++) e[j] = g_part[(size_t)row * 128 + lane * 4 + j];

    u64 m = min(min(e[0], e[1]), min(e[2], e[3]));
    #pragma unroll
    for (int o = 16; o > 0; o >>= 1) m = min(m, __shfl_xor_sync(0xffffffffu, m, o));
    float thr = unpackd(m) + g_thrpad;

    u64 best = ~0ull;
    #pragma unroll
    for (int t = 0; t < 2; t++) {
        float f1 = unpackd(e[2 * t]);
        float f2 = unpackd(e[2 * t + 1]);
        bool full = (f2 <= thr);
        bool single = (!full) && (f1 <= thr);
        int myidx = (int)(e[2 * t] & 0xFFFFFFFFu);
        unsigned msing = __ballot_sync(0xffffffffu, single);
        unsigned mfull = __ballot_sync(0xffffffffu, full);
        while (msing) {
            int src = __ffs(msing) - 1; msing &= msing - 1;
            int k = __shfl_sync(0xffffffffu, myidx, src);
            best = min(best, exact_pk(E, xv, lane, k));
        }
        while (mfull) {
            int src = __ffs(mfull) - 1; mfull &= mfull - 1;
            int k0 = (src * 2 + t) * 128;
            for (int k = k0; k < k0 + 128; k++)
                best = min(best, exact_pk(E, xv, lane, k));
        }
    }
    if (lane == 0) {
        int k = (int)(best & 0xFFFFFFFFu);
        g_idx[row] = k;
        out[IDX_OFF + row] = (float)k;
    }
}

// ---------------- final gather + loss ----------------
__global__ void final_kernel(const float* __restrict__ hs,
                             const float* __restrict__ E,
                             float* __restrict__ out) {
    __shared__ int sIdx[128];
    __shared__ float sRed[8];
    int tid = threadIdx.x;
    int row0 = blockIdx.x * 128;
    int b = row0 >> 10, p0 = row0 & 1023;
    size_t xbase = (size_t)b * 256 * 1024 + p0;

    if (tid < 128) sIdx[tid] = g_idx[row0 + tid];
    __syncthreads();

    float lsum = 0.0f;
    #pragma unroll 4
    for (int i = 0; i < 128; i++) {
        int lin = i * 256 + tid;
        int c = lin >> 7, r = lin & 127;
        int k = sIdx[r];
        float ev = __ldg(E + (size_t)k * D + c);
        size_t ad = xbase + (size_t)c * 1024 + r;
        float xv = hs[ad];
        out[ad] = ev;
        float dlt = ev - xv;
        lsum = fmaf(dlt, dlt, lsum);
    }
    #pragma unroll
    for (int o = 16; o > 0; o >>= 1) lsum += __shfl_xor_sync(0xffffffffu, lsum, o);
    if ((tid & 31) == 0) sRed[tid >> 5] = lsum;
    __syncthreads();
    if (tid == 0) {
        float tot = 0.0f;
        #pragma unroll
        for (int w = 0; w < 8; w++) tot += sRed[w];
        atomicAdd(out + LOSS_OFF, tot * (1.25f / 4194304.0f));
    }
}

extern "C" void kernel_launch(void* const* d_in, const int* in_sizes, int n_in,
                              void* d_out, int out_size) {
    const float* hs = (const float*)d_in[0];
    const float* E  = (const float*)d_in[1];
    float* out = (float*)d_out;

    cudaFuncSetAttribute(gemm_kernel,
                         cudaFuncAttributeMaxDynamicSharedMemorySize, SMEM_SZ);

    init_kernel<<<N_ROWS / 256, 256>>>(out);
    enorm_kernel<<<KC / 8, 256>>>(E);
    prepB_kernel<<<(KC * D / 4) / 256, 256>>>(E);
    prepA_kernel<<<dim3(N_ROWS / 32, D / 32), dim3(32, 8)>>>(hs);
    bound_kernel<<<1, 256>>>();
    gemm_kernel<<<dim3(KC / 128, N_ROWS / 128), 256, SMEM_SZ>>>();
    merge_kernel<<<N_ROWS / 8, 256>>>(hs, E, out);
    final_kernel<<<N_ROWS / 128, 256>>>(hs, E, out);
}